// round 3
// baseline (speedup 1.0000x reference)
#include <cuda_runtime.h>

#define NB 8
#define NC 10
#define NH 192
#define NW 192
#define HW (NH*NW)
#define CHW (NC*HW)

#define TX 32
#define TY 8
#define TW_ (TX+2)
#define TH_ (TY+2)
#define TSZ (TW_*TH_)
#define WPAD 12

typedef unsigned long long ull;

// ---------------- scratch (static device globals; no allocation) ----------------
__device__ float g_a1[NB*CHW];     // f1 * att[:,1]
__device__ float g_a2[NB*CHW];     // f1 * att[:,2]

__device__ __forceinline__ float sigmoidf_(float x){ return 1.0f/(1.0f+expf(-x)); }

__device__ __forceinline__ ull pack2(float v){
    ull r; unsigned u = __float_as_uint(v);
    asm("mov.b64 %0, {%1, %1};" : "=l"(r) : "r"(u));
    return r;
}
__device__ __forceinline__ void ffma2(ull &a, ull w, ull v){
    asm("fma.rn.f32x2 %0, %1, %2, %0;" : "+l"(a) : "l"(w), "l"(v));
}
__device__ __forceinline__ void unpack2(ull a, float &lo, float &hi){
    unsigned l, h;
    asm("mov.b64 {%0, %1}, %2;" : "=r"(l), "=r"(h) : "l"(a));
    lo = __uint_as_float(l); hi = __uint_as_float(h);
}

__device__ __forceinline__ float4 f4fma(float s, float4 v, float4 a){
    return make_float4(fmaf(s,v.x,a.x), fmaf(s,v.y,a.y), fmaf(s,v.z,a.z), fmaf(s,v.w,a.w));
}
__device__ __forceinline__ float4 f4s(float s){ return make_float4(s,s,s,s); }

// ================= Kernel 1: pointwise attention / maps + slot0 copy =================
__global__ __launch_bounds__(256) void k1_pointwise(
    const float* __restrict__ f_nodes,
    const float* __restrict__ h_nodes,
    const float* __restrict__ p_nodes,
    const float* __restrict__ w_dmap, const float* __restrict__ b_dmap,
    const float* __restrict__ w_cau,  const float* __restrict__ b_cau,
    const float* __restrict__ w_cal,  const float* __restrict__ b_cal,
    float* __restrict__ out_decomp, float* __restrict__ out_cmu, float* __restrict__ out_cml,
    float* __restrict__ out_xh)
{
    __shared__ float s_wd[90], s_bd[3], s_wcau[40], s_wcal[20], s_bc[2];
    int t = threadIdx.x;
    if (t < 90)              s_wd[t]        = w_dmap[t];
    if (t >= 96 && t < 99)   s_bd[t-96]     = b_dmap[t-96];
    if (t >= 128 && t < 168) s_wcau[t-128]  = w_cau[t-128];
    if (t >= 192 && t < 212) s_wcal[t-192]  = w_cal[t-192];
    if (t == 224) s_bc[0] = b_cau[0];
    if (t == 225) s_bc[1] = b_cal[0];
    __syncthreads();

    int pix = (blockIdx.x*256 + t)*4;           // 4 pixels per thread, NB*HW multiple of 1024
    int b = pix / HW, p = pix - b*HW;           // p aligned to 4

    const float* f1b = f_nodes + (size_t)(1*NB + b)*CHW + p;
    const float* h1b = h_nodes + (size_t)(1*NB + b)*CHW + p;
    const float* h2b = h_nodes + (size_t)(2*NB + b)*CHW + p;

    float4 f[10];
    float4 dm0 = f4s(s_bd[0]), dm1 = f4s(s_bd[1]), dm2 = f4s(s_bd[2]);
    #pragma unroll
    for (int c=0;c<10;c++){
        f[c]       = *(const float4*)(f1b + c*HW);
        float4 u1  = *(const float4*)(h1b + c*HW);
        float4 u2  = *(const float4*)(h2b + c*HW);
        dm0 = f4fma(s_wd[ 0+c],f[c],dm0); dm0 = f4fma(s_wd[10+c],u1,dm0); dm0 = f4fma(s_wd[20+c],u2,dm0);
        dm1 = f4fma(s_wd[30+c],f[c],dm1); dm1 = f4fma(s_wd[40+c],u1,dm1); dm1 = f4fma(s_wd[50+c],u2,dm1);
        dm2 = f4fma(s_wd[60+c],f[c],dm2); dm2 = f4fma(s_wd[70+c],u1,dm2); dm2 = f4fma(s_wd[80+c],u2,dm2);
    }

    // softmax over 3 channels, per component
    float4 att1, att2;
    {
        float d0v[4] = {dm0.x,dm0.y,dm0.z,dm0.w};
        float d1v[4] = {dm1.x,dm1.y,dm1.z,dm1.w};
        float d2v[4] = {dm2.x,dm2.y,dm2.z,dm2.w};
        float a1v[4], a2v[4];
        #pragma unroll
        for (int i=0;i<4;i++){
            float mx = fmaxf(d0v[i], fmaxf(d1v[i], d2v[i]));
            float e0 = expf(d0v[i]-mx), e1 = expf(d1v[i]-mx), e2 = expf(d2v[i]-mx);
            float inv = 1.0f/(e0+e1+e2);
            a1v[i] = e1*inv; a2v[i] = e2*inv;
        }
        att1 = make_float4(a1v[0],a1v[1],a1v[2],a1v[3]);
        att2 = make_float4(a2v[0],a2v[1],a2v[2],a2v[3]);
    }

    float* a1p = g_a1 + (size_t)b*CHW + p;
    float* a2p = g_a2 + (size_t)b*CHW + p;
    #pragma unroll
    for (int c=0;c<10;c++){
        *(float4*)(a1p + c*HW) = make_float4(f[c].x*att1.x, f[c].y*att1.y, f[c].z*att1.z, f[c].w*att1.w);
        *(float4*)(a2p + c*HW) = make_float4(f[c].x*att2.x, f[c].y*att2.y, f[c].z*att2.z, f[c].w*att2.w);
    }

    *(float4*)(out_decomp + (size_t)(b*3+0)*HW + p) = dm0;
    *(float4*)(out_decomp + (size_t)(b*3+1)*HW + p) = dm1;
    *(float4*)(out_decomp + (size_t)(b*3+2)*HW + p) = dm2;

    // comp_map_u: 1x1 conv over parts 1..4 (40 ch) -> sigmoid
    float4 su = f4s(s_bc[0]);
    #pragma unroll
    for (int j=0;j<4;j++){
        const float* pp = p_nodes + (size_t)((j+1)*NB + b)*CHW + p;
        #pragma unroll
        for (int c=0;c<10;c++) su = f4fma(s_wcau[j*10+c], *(const float4*)(pp + c*HW), su);
    }
    float4 mu = make_float4(sigmoidf_(su.x), sigmoidf_(su.y), sigmoidf_(su.z), sigmoidf_(su.w));
    *(float4*)(out_cmu + (size_t)b*HW + p) = mu;

    // comp_map_l: parts 5..6 (20 ch)
    float4 sl = f4s(s_bc[1]);
    #pragma unroll
    for (int j=0;j<2;j++){
        const float* pp = p_nodes + (size_t)((j+5)*NB + b)*CHW + p;
        #pragma unroll
        for (int c=0;c<10;c++) sl = f4fma(s_wcal[j*10+c], *(const float4*)(pp + c*HW), sl);
    }
    float4 ml = make_float4(sigmoidf_(sl.x), sigmoidf_(sl.y), sigmoidf_(sl.z), sigmoidf_(sl.w));
    *(float4*)(out_cml + (size_t)b*HW + p) = ml;

    // slot-0 copy: xh_new[0] = h_nodes[0]
    const float* h0 = h_nodes + (size_t)b*CHW + p;
    float* o0 = out_xh + (size_t)b*CHW + p;
    #pragma unroll
    for (int c=0;c<10;c++) *(float4*)(o0 + c*HW) = *(const float4*)(h0 + c*HW);
}

// ================= Kernel 2: fused 3x3 convs + GRU =================
// weight smem layout: s_w[(ci*9+k)*WPAD + o], WPAD=12 floats (48B) so each k-row
// is 16B aligned; output-channel pairs loaded as ulonglong2/ull for fma.rn.f32x2.
__device__ __forceinline__ void conv2(ull acc[5], const float (*tile)[TSZ],
                                      const float* swt, int cibase, int tx, int ty)
{
    #pragma unroll 1
    for (int ci=0; ci<10; ci++){
        const float* wb = swt + (cibase+ci)*9*WPAD;
        #pragma unroll
        for (int k=0; k<9; k++){
            int dy = k/3, dx = k-dy*3;
            ull vv = pack2(tile[ci][(ty+dy)*TW_ + tx+dx]);
            const ull* wp = (const ull*)(wb + k*WPAD);
            ulonglong2 p01 = *(const ulonglong2*)wp;
            ulonglong2 p23 = *(const ulonglong2*)(wp+2);
            ull p4 = wp[4];
            ffma2(acc[0], p01.x, vv); ffma2(acc[1], p01.y, vv);
            ffma2(acc[2], p23.x, vv); ffma2(acc[3], p23.y, vv);
            ffma2(acc[4], p4, vv);
        }
    }
}

// one pass over the tile feeding two accumulator sets (shared v loads)
__device__ __forceinline__ void conv2_dual(ull accD[5], ull accA[5], const float (*tile)[TSZ],
                                           const float* swtD, const float* swtA, int tx, int ty)
{
    #pragma unroll 1
    for (int ci=0; ci<10; ci++){
        const float* wbD = swtD + ci*9*WPAD;
        const float* wbA = swtA + ci*9*WPAD;
        #pragma unroll
        for (int k=0; k<9; k++){
            int dy = k/3, dx = k-dy*3;
            ull vv = pack2(tile[ci][(ty+dy)*TW_ + tx+dx]);
            {
                const ull* wp = (const ull*)(wbD + k*WPAD);
                ulonglong2 p01 = *(const ulonglong2*)wp;
                ulonglong2 p23 = *(const ulonglong2*)(wp+2);
                ull p4 = wp[4];
                ffma2(accD[0], p01.x, vv); ffma2(accD[1], p01.y, vv);
                ffma2(accD[2], p23.x, vv); ffma2(accD[3], p23.y, vv);
                ffma2(accD[4], p4, vv);
            }
            {
                const ull* wp = (const ull*)(wbA + k*WPAD);
                ulonglong2 p01 = *(const ulonglong2*)wp;
                ulonglong2 p23 = *(const ulonglong2*)(wp+2);
                ull p4 = wp[4];
                ffma2(accA[0], p01.x, vv); ffma2(accA[1], p01.y, vv);
                ffma2(accA[2], p23.x, vv); ffma2(accA[3], p23.y, vv);
                ffma2(accA[4], p4, vv);
            }
        }
    }
}

__global__ __launch_bounds__(256) void k2_conv(
    const float* __restrict__ h_nodes, const float* __restrict__ p_nodes,
    const float* __restrict__ mapu, const float* __restrict__ mapl,
    const float* __restrict__ w_decomp, const float* __restrict__ g_decomp, const float* __restrict__ be_decomp,
    const float* __restrict__ w_cu, const float* __restrict__ g_cu, const float* __restrict__ be_cu,
    const float* __restrict__ w_cl, const float* __restrict__ g_cl, const float* __restrict__ be_cl,
    const float* __restrict__ wg_u, const float* __restrict__ bg_u,
    const float* __restrict__ wc_u, const float* __restrict__ g_u, const float* __restrict__ be_u,
    const float* __restrict__ wg_l, const float* __restrict__ bg_l,
    const float* __restrict__ wc_l, const float* __restrict__ g_l, const float* __restrict__ be_l,
    float* __restrict__ out_xh)
{
    __shared__ __align__(16) float s_wdt[180*WPAD];
    __shared__ __align__(16) float s_wct[180*WPAD];
    __shared__ float s_tile[10][TSZ];
    __shared__ float s_map[TSZ];
    __shared__ float s_gd[10], s_bed[10], s_gc[10], s_bec[10];
    __shared__ float s_wg[40], s_bg[2], s_wc[200], s_gg[10], s_beg[10];

    int z = blockIdx.z; int b = z >> 1; int half = z & 1;
    const float* wc   = half ? w_cl  : w_cu;
    const float* gcv  = half ? g_cl  : g_cu;
    const float* becv = half ? be_cl : be_cu;
    const float* aX   = (half ? g_a2 : g_a1) + (size_t)b*CHW;
    const float* hX   = h_nodes + (size_t)((half?2:1)*NB + b)*CHW;
    const float* mapX = (half ? mapl : mapu) + (size_t)b*HW;
    const float* wgv  = half ? wg_l : wg_u;
    const float* bgv  = half ? bg_l : bg_u;
    const float* wcv  = half ? wc_l : wc_u;
    const float* ggv  = half ? g_l  : g_u;
    const float* bev  = half ? be_l : be_u;
    float* outp       = out_xh + (size_t)((half?2:1)*NB + b)*CHW;
    int nparts = half ? 2 : 4;
    int pbase  = half ? 5 : 1;

    int tid = threadIdx.y*TX + threadIdx.x;
    for (int i=tid; i<1800; i+=256){
        int o = i/180, r = i - o*180, c = r/9, k = r - c*9;
        s_wdt[(c*9+k)*WPAD + o] = w_decomp[i];
        s_wct[(c*9+k)*WPAD + o] = wc[i];
    }
    if (tid < 10){
        s_gd[tid]=g_decomp[tid]; s_bed[tid]=be_decomp[tid];
        s_gc[tid]=gcv[tid];      s_bec[tid]=becv[tid];
        s_gg[tid]=ggv[tid];      s_beg[tid]=bev[tid];
    }
    if (tid >= 32 && tid < 72)  s_wg[tid-32] = wgv[tid-32];
    if (tid == 72) { s_bg[0]=bgv[0]; s_bg[1]=bgv[1]; }
    for (int i=tid; i<200; i+=256) s_wc[i] = wcv[i];     // FIX: full 200-elem load

    int x0 = blockIdx.x*TX, y0 = blockIdx.y*TY;

    // map tile (with halo)
    for (int j=tid; j<TSZ; j+=256){
        int r=j/TW_, c=j-r*TW_;
        int gy=y0-1+r, gx=x0-1+c;
        s_map[j] = (gy>=0 && gy<NH && gx>=0 && gx<NW) ? mapX[gy*NW+gx] : 0.0f;
    }
    // a tile group
    for (int i=tid; i<10*TSZ; i+=256){
        int ci=i/TSZ, j=i-ci*TSZ;
        int r=j/TW_, c=j-r*TW_;
        int gy=y0-1+r, gx=x0-1+c;
        s_tile[ci][j] = (gy>=0 && gy<NH && gx>=0 && gx<NW) ? aX[(size_t)ci*HW + gy*NW + gx] : 0.0f;
    }
    __syncthreads();

    int tx = threadIdx.x, ty = threadIdx.y;
    ull aD[5] = {0,0,0,0,0};
    conv2(aD, s_tile, s_wdt, 0, tx, ty);                // w_decomp[:, 0:10] * (f*att)
    __syncthreads();

    // h tile group
    for (int i=tid; i<10*TSZ; i+=256){
        int ci=i/TSZ, j=i-ci*TSZ;
        int r=j/TW_, c=j-r*TW_;
        int gy=y0-1+r, gx=x0-1+c;
        s_tile[ci][j] = (gy>=0 && gy<NH && gx>=0 && gx<NW) ? hX[(size_t)ci*HW + gy*NW + gx] : 0.0f;
    }
    __syncthreads();

    ull aA[5] = {0,0,0,0,0};
    conv2_dual(aD, aA, s_tile, s_wdt + 10*9*WPAD, s_wct, tx, ty);

    // stash center h values before tile is overwritten
    float hcen[10];
    #pragma unroll
    for (int ci=0; ci<10; ci++) hcen[ci] = s_tile[ci][(ty+1)*TW_ + tx+1];

    float msgv[10];
    #pragma unroll
    for (int i=0;i<5;i++){
        float lo, hi; unpack2(aD[i], lo, hi);
        msgv[2*i]   = fmaxf(fmaf(s_gd[2*i],   lo, s_bed[2*i]),   0.0f);
        msgv[2*i+1] = fmaxf(fmaf(s_gd[2*i+1], hi, s_bed[2*i+1]), 0.0f);
    }

    for (int part=0; part<nparts; part++){
        const float* pX = p_nodes + (size_t)((pbase+part)*NB + b)*CHW;
        __syncthreads();
        for (int i=tid; i<10*TSZ; i+=256){
            int ci=i/TSZ, j=i-ci*TSZ;
            int r=j/TW_, c=j-r*TW_;
            int gy=y0-1+r, gx=x0-1+c;
            s_tile[ci][j] = (gy>=0 && gy<NH && gx>=0 && gx<NW)
                          ? pX[(size_t)ci*HW + gy*NW + gx] * s_map[j] : 0.0f;
        }
        __syncthreads();
        ull acc[5];
        #pragma unroll
        for (int i=0;i<5;i++) acc[i]=aA[i];
        conv2(acc, s_tile, s_wct, 10, tx, ty);          // w_c[:, 10:20] * (p*map)
        #pragma unroll
        for (int i=0;i<5;i++){
            float lo, hi; unpack2(acc[i], lo, hi);
            msgv[2*i]   += fmaxf(fmaf(s_gc[2*i],   lo, s_bec[2*i]),   0.0f);
            msgv[2*i+1] += fmaxf(fmaf(s_gc[2*i+1], hi, s_bec[2*i+1]), 0.0f);
        }
    }

    // ---------- GRU epilogue (pointwise) ----------
    float g0 = s_bg[0], g1 = s_bg[1];
    #pragma unroll
    for (int c=0;c<10;c++){
        g0 = fmaf(s_wg[c],    msgv[c], g0);
        g0 = fmaf(s_wg[10+c], hcen[c], g0);
        g1 = fmaf(s_wg[20+c], msgv[c], g1);
        g1 = fmaf(s_wg[30+c], hcen[c], g1);
    }
    float rr = sigmoidf_(g0), uu = sigmoidf_(g1);
    float rh[10];
    #pragma unroll
    for (int c=0;c<10;c++) rh[c] = rr*hcen[c];

    int px = x0+tx, py = y0+ty;
    float* op = outp + py*NW + px;
    #pragma unroll
    for (int o=0;o<10;o++){
        float s = 0.0f;
        #pragma unroll
        for (int c=0;c<10;c++){
            s = fmaf(s_wc[o*20+c],    msgv[c], s);
            s = fmaf(s_wc[o*20+10+c], rh[c],   s);
        }
        float cn = fmaf(s_gg[o], s, s_beg[o]);
        cn = cn > 0.0f ? cn : 0.01f*cn;                 // leaky_relu 0.01
        op[(size_t)o*HW] = (1.0f-uu)*hcen[o] + uu*cn;
    }
}

// ================= launcher =================
extern "C" void kernel_launch(void* const* d_in, const int* in_sizes, int n_in,
                              void* d_out, int out_size)
{
    const float* f_nodes  = (const float*)d_in[0];
    const float* h_nodes  = (const float*)d_in[1];
    const float* p_nodes  = (const float*)d_in[2];
    // d_in[3] = xh (unused by reference)
    const float* w_dmap   = (const float*)d_in[4];
    const float* b_dmap   = (const float*)d_in[5];
    const float* w_decomp = (const float*)d_in[6];
    const float* g_decomp = (const float*)d_in[7];
    const float* be_decomp= (const float*)d_in[8];
    const float* w_cau    = (const float*)d_in[9];
    const float* b_cau    = (const float*)d_in[10];
    const float* w_cal    = (const float*)d_in[11];
    const float* b_cal    = (const float*)d_in[12];
    const float* w_cu     = (const float*)d_in[13];
    const float* g_cu     = (const float*)d_in[14];
    const float* be_cu    = (const float*)d_in[15];
    const float* w_cl     = (const float*)d_in[16];
    const float* g_cl     = (const float*)d_in[17];
    const float* be_cl    = (const float*)d_in[18];
    const float* wg_u     = (const float*)d_in[19];
    const float* bg_u     = (const float*)d_in[20];
    const float* wc_u     = (const float*)d_in[21];
    const float* g_u      = (const float*)d_in[22];
    const float* be_u     = (const float*)d_in[23];
    const float* wg_l     = (const float*)d_in[24];
    const float* bg_l     = (const float*)d_in[25];
    const float* wc_l     = (const float*)d_in[26];
    const float* g_l      = (const float*)d_in[27];
    const float* be_l     = (const float*)d_in[28];

    float* out        = (float*)d_out;
    float* out_decomp = out + (size_t)3*NB*CHW;      // xh_new is 3*B*10*H*W
    float* out_cmu    = out_decomp + (size_t)NB*3*HW;
    float* out_cml    = out_cmu + (size_t)NB*HW;

    k1_pointwise<<<NB*HW/1024, 256>>>(f_nodes, h_nodes, p_nodes,
                                      w_dmap, b_dmap, w_cau, b_cau, w_cal, b_cal,
                                      out_decomp, out_cmu, out_cml, out);

    dim3 g2(NW/TX, NH/TY, 2*NB), b2(TX, TY);
    k2_conv<<<g2, b2>>>(h_nodes, p_nodes, out_cmu, out_cml,
                        w_decomp, g_decomp, be_decomp,
                        w_cu, g_cu, be_cu,
                        w_cl, g_cl, be_cl,
                        wg_u, bg_u, wc_u, g_u, be_u,
                        wg_l, bg_l, wc_l, g_l, be_l,
                        out);
}

// round 4
// speedup vs baseline: 1.4988x; 1.4988x over previous
#include <cuda_runtime.h>

#define NB 8
#define NC 10
#define NH 192
#define NW 192
#define HW (NH*NW)
#define CHW (NC*HW)

#define TX 32
#define TY 8
#define TW_ (TX+2)
#define TH_ (TY+2)
#define TSZ (TW_*TH_)
#define WPAD 12
#define NLD 14            /* ceil(10*TSZ/256) */

// ---------------- scratch (static device globals; no allocation) ----------------
__device__ float g_a1[NB*CHW];     // f1 * att[:,1]
__device__ float g_a2[NB*CHW];     // f1 * att[:,2]

__device__ __forceinline__ float sigmoidf_(float x){ return 1.0f/(1.0f+expf(-x)); }

__device__ __forceinline__ float4 f4fma(float s, float4 v, float4 a){
    return make_float4(fmaf(s,v.x,a.x), fmaf(s,v.y,a.y), fmaf(s,v.z,a.z), fmaf(s,v.w,a.w));
}
__device__ __forceinline__ float4 f4s(float s){ return make_float4(s,s,s,s); }

// ================= Kernel 1: pointwise attention / maps + slot0 copy =================
__global__ __launch_bounds__(256) void k1_pointwise(
    const float* __restrict__ f_nodes,
    const float* __restrict__ h_nodes,
    const float* __restrict__ p_nodes,
    const float* __restrict__ w_dmap, const float* __restrict__ b_dmap,
    const float* __restrict__ w_cau,  const float* __restrict__ b_cau,
    const float* __restrict__ w_cal,  const float* __restrict__ b_cal,
    float* __restrict__ out_decomp, float* __restrict__ out_cmu, float* __restrict__ out_cml,
    float* __restrict__ out_xh)
{
    __shared__ float s_wd[90], s_bd[3], s_wcau[40], s_wcal[20], s_bc[2];
    int t = threadIdx.x;
    if (t < 90)              s_wd[t]        = w_dmap[t];
    if (t >= 96 && t < 99)   s_bd[t-96]     = b_dmap[t-96];
    if (t >= 128 && t < 168) s_wcau[t-128]  = w_cau[t-128];
    if (t >= 192 && t < 212) s_wcal[t-192]  = w_cal[t-192];
    if (t == 224) s_bc[0] = b_cau[0];
    if (t == 225) s_bc[1] = b_cal[0];
    __syncthreads();

    int pix = (blockIdx.x*256 + t)*4;           // 4 pixels per thread
    int b = pix / HW, p = pix - b*HW;           // p aligned to 4

    const float* f1b = f_nodes + (size_t)(1*NB + b)*CHW + p;
    const float* h1b = h_nodes + (size_t)(1*NB + b)*CHW + p;
    const float* h2b = h_nodes + (size_t)(2*NB + b)*CHW + p;

    float4 f[10];
    float4 dm0 = f4s(s_bd[0]), dm1 = f4s(s_bd[1]), dm2 = f4s(s_bd[2]);
    #pragma unroll
    for (int c=0;c<10;c++){
        f[c]       = *(const float4*)(f1b + c*HW);
        float4 u1  = *(const float4*)(h1b + c*HW);
        float4 u2  = *(const float4*)(h2b + c*HW);
        dm0 = f4fma(s_wd[ 0+c],f[c],dm0); dm0 = f4fma(s_wd[10+c],u1,dm0); dm0 = f4fma(s_wd[20+c],u2,dm0);
        dm1 = f4fma(s_wd[30+c],f[c],dm1); dm1 = f4fma(s_wd[40+c],u1,dm1); dm1 = f4fma(s_wd[50+c],u2,dm1);
        dm2 = f4fma(s_wd[60+c],f[c],dm2); dm2 = f4fma(s_wd[70+c],u1,dm2); dm2 = f4fma(s_wd[80+c],u2,dm2);
    }

    float4 att1, att2;
    {
        float d0v[4] = {dm0.x,dm0.y,dm0.z,dm0.w};
        float d1v[4] = {dm1.x,dm1.y,dm1.z,dm1.w};
        float d2v[4] = {dm2.x,dm2.y,dm2.z,dm2.w};
        float a1v[4], a2v[4];
        #pragma unroll
        for (int i=0;i<4;i++){
            float mx = fmaxf(d0v[i], fmaxf(d1v[i], d2v[i]));
            float e0 = expf(d0v[i]-mx), e1 = expf(d1v[i]-mx), e2 = expf(d2v[i]-mx);
            float inv = 1.0f/(e0+e1+e2);
            a1v[i] = e1*inv; a2v[i] = e2*inv;
        }
        att1 = make_float4(a1v[0],a1v[1],a1v[2],a1v[3]);
        att2 = make_float4(a2v[0],a2v[1],a2v[2],a2v[3]);
    }

    float* a1p = g_a1 + (size_t)b*CHW + p;
    float* a2p = g_a2 + (size_t)b*CHW + p;
    #pragma unroll
    for (int c=0;c<10;c++){
        *(float4*)(a1p + c*HW) = make_float4(f[c].x*att1.x, f[c].y*att1.y, f[c].z*att1.z, f[c].w*att1.w);
        *(float4*)(a2p + c*HW) = make_float4(f[c].x*att2.x, f[c].y*att2.y, f[c].z*att2.z, f[c].w*att2.w);
    }

    *(float4*)(out_decomp + (size_t)(b*3+0)*HW + p) = dm0;
    *(float4*)(out_decomp + (size_t)(b*3+1)*HW + p) = dm1;
    *(float4*)(out_decomp + (size_t)(b*3+2)*HW + p) = dm2;

    float4 su = f4s(s_bc[0]);
    #pragma unroll
    for (int j=0;j<4;j++){
        const float* pp = p_nodes + (size_t)((j+1)*NB + b)*CHW + p;
        #pragma unroll
        for (int c=0;c<10;c++) su = f4fma(s_wcau[j*10+c], *(const float4*)(pp + c*HW), su);
    }
    float4 mu = make_float4(sigmoidf_(su.x), sigmoidf_(su.y), sigmoidf_(su.z), sigmoidf_(su.w));
    *(float4*)(out_cmu + (size_t)b*HW + p) = mu;

    float4 sl = f4s(s_bc[1]);
    #pragma unroll
    for (int j=0;j<2;j++){
        const float* pp = p_nodes + (size_t)((j+5)*NB + b)*CHW + p;
        #pragma unroll
        for (int c=0;c<10;c++) sl = f4fma(s_wcal[j*10+c], *(const float4*)(pp + c*HW), sl);
    }
    float4 ml = make_float4(sigmoidf_(sl.x), sigmoidf_(sl.y), sigmoidf_(sl.z), sigmoidf_(sl.w));
    *(float4*)(out_cml + (size_t)b*HW + p) = ml;

    const float* h0 = h_nodes + (size_t)b*CHW + p;
    float* o0 = out_xh + (size_t)b*CHW + p;
    #pragma unroll
    for (int c=0;c<10;c++) *(float4*)(o0 + c*HW) = *(const float4*)(h0 + c*HW);
}

// ================= Kernel 2: fused 3x3 convs + GRU, double-buffered tiles =================
// scalar FFMA conv (R1 design): weights in smem [(ci*9+k)*WPAD + o], 3 vector LDS
// broadcast per 10 FMAs.
__device__ __forceinline__ void conv_acc(float* acc, const float (*tile)[TSZ],
                                         const float* swt, int cibase, int tx, int ty)
{
    #pragma unroll 1
    for (int ci=0; ci<10; ci++){
        float v[9];
        #pragma unroll
        for (int dy=0; dy<3; dy++){
            #pragma unroll
            for (int dx=0; dx<3; dx++)
                v[dy*3+dx] = tile[ci][(ty+dy)*TW_ + tx+dx];
        }
        const float* wb = swt + (cibase+ci)*9*WPAD;
        #pragma unroll
        for (int k=0; k<9; k++){
            float4 wa = *(const float4*)(wb + k*WPAD);
            float4 w2 = *(const float4*)(wb + k*WPAD + 4);
            float2 w3 = *(const float2*)(wb + k*WPAD + 8);
            float vv = v[k];
            acc[0]=fmaf(wa.x,vv,acc[0]); acc[1]=fmaf(wa.y,vv,acc[1]);
            acc[2]=fmaf(wa.z,vv,acc[2]); acc[3]=fmaf(wa.w,vv,acc[3]);
            acc[4]=fmaf(w2.x,vv,acc[4]); acc[5]=fmaf(w2.y,vv,acc[5]);
            acc[6]=fmaf(w2.z,vv,acc[6]); acc[7]=fmaf(w2.w,vv,acc[7]);
            acc[8]=fmaf(w3.x,vv,acc[8]); acc[9]=fmaf(w3.y,vv,acc[9]);
        }
    }
}

// issue global loads for one 10-channel haloed tile into registers (zero-fill OOB)
__device__ __forceinline__ void stage_load(float* regs, const float* __restrict__ src,
                                           int tid, int x0, int y0)
{
    #pragma unroll
    for (int j=0;j<NLD;j++){
        int i = tid + j*256;
        float v = 0.0f;
        if (i < 10*TSZ){
            int ci = i/TSZ, jj = i - ci*TSZ;
            int r = jj/TW_, c = jj - r*TW_;
            int gy = y0-1+r, gx = x0-1+c;
            if (gy>=0 && gy<NH && gx>=0 && gx<NW) v = src[(size_t)ci*HW + gy*NW + gx];
        }
        regs[j] = v;
    }
}
__device__ __forceinline__ void stage_store(float (*buf)[TSZ], const float* regs, int tid)
{
    #pragma unroll
    for (int j=0;j<NLD;j++){
        int i = tid + j*256;
        if (i < 10*TSZ){
            int ci = i/TSZ, jj = i - ci*TSZ;
            buf[ci][jj] = regs[j];
        }
    }
}
__device__ __forceinline__ void stage_store_mul(float (*buf)[TSZ], const float* regs,
                                                const float* smap, int tid)
{
    #pragma unroll
    for (int j=0;j<NLD;j++){
        int i = tid + j*256;
        if (i < 10*TSZ){
            int ci = i/TSZ, jj = i - ci*TSZ;
            buf[ci][jj] = regs[j]*smap[jj];
        }
    }
}

__global__ __launch_bounds__(256) void k2_conv(
    const float* __restrict__ h_nodes, const float* __restrict__ p_nodes,
    const float* __restrict__ mapu, const float* __restrict__ mapl,
    const float* __restrict__ w_decomp, const float* __restrict__ g_decomp, const float* __restrict__ be_decomp,
    const float* __restrict__ w_cu, const float* __restrict__ g_cu, const float* __restrict__ be_cu,
    const float* __restrict__ w_cl, const float* __restrict__ g_cl, const float* __restrict__ be_cl,
    const float* __restrict__ wg_u, const float* __restrict__ bg_u,
    const float* __restrict__ wc_u, const float* __restrict__ g_u, const float* __restrict__ be_u,
    const float* __restrict__ wg_l, const float* __restrict__ bg_l,
    const float* __restrict__ wc_l, const float* __restrict__ g_l, const float* __restrict__ be_l,
    float* __restrict__ out_xh)
{
    __shared__ __align__(16) float s_wdt[180*WPAD];
    __shared__ __align__(16) float s_wct[180*WPAD];
    __shared__ float s_tA[10][TSZ];
    __shared__ float s_tB[10][TSZ];
    __shared__ float s_map[TSZ];
    __shared__ float s_gd[10], s_bed[10], s_gc[10], s_bec[10];
    __shared__ float s_wg[40], s_bg[2], s_wc[200], s_gg[10], s_beg[10];

    int z = blockIdx.z; int b = z >> 1; int half = z & 1;
    const float* wc   = half ? w_cl  : w_cu;
    const float* gcv  = half ? g_cl  : g_cu;
    const float* becv = half ? be_cl : be_cu;
    const float* aX   = (half ? g_a2 : g_a1) + (size_t)b*CHW;
    const float* hX   = h_nodes + (size_t)((half?2:1)*NB + b)*CHW;
    const float* mapX = (half ? mapl : mapu) + (size_t)b*HW;
    const float* wgv  = half ? wg_l : wg_u;
    const float* bgv  = half ? bg_l : bg_u;
    const float* wcv  = half ? wc_l : wc_u;
    const float* ggv  = half ? g_l  : g_u;
    const float* bev  = half ? be_l : be_u;
    float* outp       = out_xh + (size_t)((half?2:1)*NB + b)*CHW;
    int nparts = half ? 2 : 4;
    int pbase  = half ? 5 : 1;

    int tid = threadIdx.y*TX + threadIdx.x;
    int x0 = blockIdx.x*TX, y0 = blockIdx.y*TY;
    int tx = threadIdx.x, ty = threadIdx.y;

    // ---- weight + param staging ----
    for (int i=tid; i<1800; i+=256){
        int o = i/180, r = i - o*180, c = r/9, k = r - c*9;
        s_wdt[(c*9+k)*WPAD + o] = w_decomp[i];
        s_wct[(c*9+k)*WPAD + o] = wc[i];
    }
    if (tid < 10){
        s_gd[tid]=g_decomp[tid]; s_bed[tid]=be_decomp[tid];
        s_gc[tid]=gcv[tid];      s_bec[tid]=becv[tid];
        s_gg[tid]=ggv[tid];      s_beg[tid]=bev[tid];
    }
    if (tid >= 32 && tid < 72)  s_wg[tid-32] = wgv[tid-32];
    if (tid == 72) { s_bg[0]=bgv[0]; s_bg[1]=bgv[1]; }
    for (int i=tid; i<200; i+=256) s_wc[i] = wcv[i];

    // ---- prologue: map + a-tile into A ----
    for (int j=tid; j<TSZ; j+=256){
        int r=j/TW_, c=j-r*TW_;
        int gy=y0-1+r, gx=x0-1+c;
        s_map[j] = (gy>=0 && gy<NH && gx>=0 && gx<NW) ? mapX[gy*NW+gx] : 0.0f;
    }
    float regs[NLD];
    stage_load(regs, aX, tid, x0, y0);
    stage_store(s_tA, regs, tid);
    __syncthreads();

    // ---- stage A(a-tile): compute convD, load h ----
    stage_load(regs, hX, tid, x0, y0);        // LDGs in flight during conv
    float accD[10];
    #pragma unroll
    for (int o=0;o<10;o++) accD[o]=0.0f;
    conv_acc(accD, s_tA, s_wdt, 0, tx, ty);   // w_decomp[:, 0:10] * (f*att)
    stage_store(s_tB, regs, tid);
    __syncthreads();

    // ---- stage B(h-tile): compute convD part2 + shared-A, load part0 ----
    stage_load(regs, p_nodes + (size_t)(pbase*NB + b)*CHW, tid, x0, y0);
    conv_acc(accD, s_tB, s_wdt, 10, tx, ty);  // w_decomp[:, 10:20] * h
    float accA[10];
    #pragma unroll
    for (int o=0;o<10;o++) accA[o]=0.0f;
    conv_acc(accA, s_tB, s_wct, 0, tx, ty);   // shared: w_c[:, 0:10] * h

    float hcen[10];
    #pragma unroll
    for (int ci=0; ci<10; ci++) hcen[ci] = s_tB[ci][(ty+1)*TW_ + tx+1];

    float msgv[10];
    #pragma unroll
    for (int o=0;o<10;o++)
        msgv[o] = fmaxf(fmaf(s_gd[o], accD[o], s_bed[o]), 0.0f);

    stage_store_mul(s_tA, regs, s_map, tid);  // part0 * map into A
    __syncthreads();

    // ---- part loop (ping-pong A/B) ----
    for (int part=0; part<nparts; part++){
        float (*cur)[TSZ]  = (part & 1) ? s_tB : s_tA;
        float (*next)[TSZ] = (part & 1) ? s_tA : s_tB;
        bool more = (part+1 < nparts);
        if (more)
            stage_load(regs, p_nodes + (size_t)((pbase+part+1)*NB + b)*CHW, tid, x0, y0);
        float acc[10];
        #pragma unroll
        for (int o=0;o<10;o++) acc[o]=accA[o];
        conv_acc(acc, cur, s_wct, 10, tx, ty);    // w_c[:, 10:20] * (p*map)
        #pragma unroll
        for (int o=0;o<10;o++)
            msgv[o] += fmaxf(fmaf(s_gc[o], acc[o], s_bec[o]), 0.0f);
        if (more){
            stage_store_mul(next, regs, s_map, tid);
            __syncthreads();
        }
    }

    // ---------- GRU epilogue (pointwise) ----------
    float g0 = s_bg[0], g1 = s_bg[1];
    #pragma unroll
    for (int c=0;c<10;c++){
        g0 = fmaf(s_wg[c],    msgv[c], g0);
        g0 = fmaf(s_wg[10+c], hcen[c], g0);
        g1 = fmaf(s_wg[20+c], msgv[c], g1);
        g1 = fmaf(s_wg[30+c], hcen[c], g1);
    }
    float rr = sigmoidf_(g0), uu = sigmoidf_(g1);
    float rh[10];
    #pragma unroll
    for (int c=0;c<10;c++) rh[c] = rr*hcen[c];

    int px = x0+tx, py = y0+ty;
    float* op = outp + py*NW + px;
    #pragma unroll
    for (int o=0;o<10;o++){
        float s = 0.0f;
        #pragma unroll
        for (int c=0;c<10;c++){
            s = fmaf(s_wc[o*20+c],    msgv[c], s);
            s = fmaf(s_wc[o*20+10+c], rh[c],   s);
        }
        float cn = fmaf(s_gg[o], s, s_beg[o]);
        cn = cn > 0.0f ? cn : 0.01f*cn;          // leaky_relu 0.01
        op[(size_t)o*HW] = (1.0f-uu)*hcen[o] + uu*cn;
    }
}

// ================= launcher =================
extern "C" void kernel_launch(void* const* d_in, const int* in_sizes, int n_in,
                              void* d_out, int out_size)
{
    const float* f_nodes  = (const float*)d_in[0];
    const float* h_nodes  = (const float*)d_in[1];
    const float* p_nodes  = (const float*)d_in[2];
    const float* w_dmap   = (const float*)d_in[4];
    const float* b_dmap   = (const float*)d_in[5];
    const float* w_decomp = (const float*)d_in[6];
    const float* g_decomp = (const float*)d_in[7];
    const float* be_decomp= (const float*)d_in[8];
    const float* w_cau    = (const float*)d_in[9];
    const float* b_cau    = (const float*)d_in[10];
    const float* w_cal    = (const float*)d_in[11];
    const float* b_cal    = (const float*)d_in[12];
    const float* w_cu     = (const float*)d_in[13];
    const float* g_cu     = (const float*)d_in[14];
    const float* be_cu    = (const float*)d_in[15];
    const float* w_cl     = (const float*)d_in[16];
    const float* g_cl     = (const float*)d_in[17];
    const float* be_cl    = (const float*)d_in[18];
    const float* wg_u     = (const float*)d_in[19];
    const float* bg_u     = (const float*)d_in[20];
    const float* wc_u     = (const float*)d_in[21];
    const float* g_u      = (const float*)d_in[22];
    const float* be_u     = (const float*)d_in[23];
    const float* wg_l     = (const float*)d_in[24];
    const float* bg_l     = (const float*)d_in[25];
    const float* wc_l     = (const float*)d_in[26];
    const float* g_l      = (const float*)d_in[27];
    const float* be_l     = (const float*)d_in[28];

    float* out        = (float*)d_out;
    float* out_decomp = out + (size_t)3*NB*CHW;
    float* out_cmu    = out_decomp + (size_t)NB*3*HW;
    float* out_cml    = out_cmu + (size_t)NB*HW;

    k1_pointwise<<<NB*HW/1024, 256>>>(f_nodes, h_nodes, p_nodes,
                                      w_dmap, b_dmap, w_cau, b_cau, w_cal, b_cal,
                                      out_decomp, out_cmu, out_cml, out);

    dim3 g2(NW/TX, NH/TY, 2*NB), b2(TX, TY);
    k2_conv<<<g2, b2>>>(h_nodes, p_nodes, out_cmu, out_cml,
                        w_decomp, g_decomp, be_decomp,
                        w_cu, g_cu, be_cu,
                        w_cl, g_cl, be_cl,
                        wg_u, bg_u, wc_u, g_u, be_u,
                        wg_l, bg_l, wc_l, g_l, be_l,
                        out);
}